// round 2
// baseline (speedup 1.0000x reference)
#include <cuda_runtime.h>
#include <math.h>

#define Nn 8192
#define Dn 2048
#define Kn 256
#define NBLK 148

// ---------------- device scratch (static: no allocation allowed) ----------------
__device__ float g_C[(size_t)Dn * Dn];     // 16 MB  C = x^T x
__device__ float g_Vt[(size_t)Kn * Dn];    // Vt[k][d] = V0[d][k]
__device__ float g_WT[(size_t)Dn * Kn];    // WT[d][j] = w_j[d]
__device__ float g_VnT[(size_t)Dn * Kn];   // VnT[d][j] = vn_j[d]
__device__ float g_a[Dn];
__device__ float g_u[Dn];
__device__ float g_c1[2][Kn];              // vn_j . v_{k}   (double buffered)
__device__ float g_c3[2][Kn];              // vn_j . u       (double buffered)
__device__ float g_g[Kn];                  // w_j . b
__device__ float g_d0[Kn];
__device__ float g_dn2[2];
__device__ float g_uv[2];
__device__ unsigned g_barcnt;
__device__ unsigned g_bargen;
__device__ unsigned g_done;

// ---------------- grid barrier (all NBLK CTAs co-resident: grid <= #SMs) -------
__device__ __forceinline__ unsigned ldv_u32(const unsigned* p) {
    unsigned v;
    asm volatile("ld.volatile.global.u32 %0, [%1];" : "=r"(v) : "l"(p));
    return v;
}

__device__ __forceinline__ void gbar(unsigned& gen) {
    ++gen;
    __syncthreads();
    if (threadIdx.x == 0) {
        __threadfence();
        unsigned tick = atomicAdd(&g_barcnt, 1u);
        if (tick == (unsigned)(gridDim.x - 1)) {
            g_barcnt = 0u;
            __threadfence();
            atomicExch(&g_bargen, gen);
        } else {
            while (ldv_u32(&g_bargen) < gen) { }
        }
        __threadfence();
    }
    __syncthreads();
}

// ---------------- prep: transpose V0 -> Vt, per-column norms d0 ----------------
__global__ void __launch_bounds__(256) prep_kernel(const float* __restrict__ V0) {
    __shared__ float sb[8];
    int k = blockIdx.x;
    float s = 0.f;
    for (int d = threadIdx.x; d < Dn; d += 256) {
        float v = V0[(size_t)d * Kn + k];
        g_Vt[(size_t)k * Dn + d] = v;
        s += v * v;
    }
    #pragma unroll
    for (int o = 16; o; o >>= 1) s += __shfl_down_sync(~0u, s, o);
    if ((threadIdx.x & 31) == 0) sb[threadIdx.x >> 5] = s;
    __syncthreads();
    if (threadIdx.x == 0) {
        float t = 0.f;
        #pragma unroll
        for (int w = 0; w < 8; ++w) t += sb[w];
        g_d0[k] = sqrtf(t);
    }
}

// ---------------- C = x^T x (symmetric: 136 upper-tri 128x128 tile pairs) ------
__global__ void __launch_bounds__(256) gemmC_kernel(const float* __restrict__ x) {
    __shared__ __align__(16) float As[16][128];
    __shared__ __align__(16) float Bs[16][128];

    int rem = blockIdx.x, bi = 0, width = 16;
    while (rem >= width) { rem -= width; ++bi; --width; }
    int bj = bi + rem;

    const int tid = threadIdx.x;
    const int ty = tid >> 4, tx = tid & 15;
    float acc[8][8];
    #pragma unroll
    for (int p = 0; p < 8; ++p)
        #pragma unroll
        for (int q = 0; q < 8; ++q) acc[p][q] = 0.f;

    for (int n0 = 0; n0 < Nn; n0 += 16) {
        #pragma unroll
        for (int it = 0; it < 2; ++it) {
            int idx = tid + it * 256;           // 0..511
            int r = idx >> 5;                   // 0..15
            int c4 = idx & 31;                  // 0..31 (float4 within 128 cols)
            const float4* xr = (const float4*)(x + (size_t)(n0 + r) * Dn);
            ((float4*)&As[r][0])[c4] = xr[bi * 32 + c4];
            ((float4*)&Bs[r][0])[c4] = xr[bj * 32 + c4];
        }
        __syncthreads();
        #pragma unroll
        for (int kk = 0; kk < 16; ++kk) {
            float a8[8], b8[8];
            *(float4*)&a8[0] = *(const float4*)&As[kk][ty * 8];
            *(float4*)&a8[4] = *(const float4*)&As[kk][ty * 8 + 4];
            *(float4*)&b8[0] = *(const float4*)&Bs[kk][tx * 8];
            *(float4*)&b8[4] = *(const float4*)&Bs[kk][tx * 8 + 4];
            #pragma unroll
            for (int p = 0; p < 8; ++p)
                #pragma unroll
                for (int q = 0; q < 8; ++q) acc[p][q] += a8[p] * b8[q];
        }
        __syncthreads();
    }

    int gi = bi * 128 + ty * 8;
    int gj = bj * 128 + tx * 8;
    #pragma unroll
    for (int p = 0; p < 8; ++p) {
        float* dst = g_C + (size_t)(gi + p) * Dn + gj;
        *(float4*)(dst)     = make_float4(acc[p][0], acc[p][1], acc[p][2], acc[p][3]);
        *(float4*)(dst + 4) = make_float4(acc[p][4], acc[p][5], acc[p][6], acc[p][7]);
    }
    if (bi != bj) {
        #pragma unroll
        for (int q = 0; q < 8; ++q) {
            float* dst = g_C + (size_t)(gj + q) * Dn + gi;
            *(float4*)(dst)     = make_float4(acc[0][q], acc[1][q], acc[2][q], acc[3][q]);
            *(float4*)(dst + 4) = make_float4(acc[4][q], acc[5][q], acc[6][q], acc[7][q]);
        }
    }
}

// ---------------- persistent sequential CCIPCA solve ----------------
// Step k, 3 grid barriers:
//  P1: vn_{k-1} = s*u ; w_{k-1} = vn_{k-1} - sum_{j<k-1} (s*c3_j) w_j ;
//      a = v_k - sum_{j<k-1} c1_j w_j - (s*uv) w_{k-1}
//  P2: b = C a (own row slice) ; partial g_j += w_j . b (atomics)
//  P3: u = 0.5 v_k + (0.5/d0_k)(b - sum_j g_j vn_j) ;
//      partial dots for next step: c3_j += vn_j.u ; c1_j += vn_j.v_{k+1} ;
//      dn2 += u^2 ; uv += u.v_{k+1}
__global__ void __launch_bounds__(256) solve_kernel() {
    __shared__ __align__(16) float s_a[Dn];   // 8 KB
    __shared__ float sc3s[Kn], sc1[Kn], s_g[Kn];
    __shared__ float s_b[16], s_u[16], s_vk1[16];

    const int tid = threadIdx.x;
    const int bid = blockIdx.x;
    const int wid = tid >> 5, lane = tid & 31;
    int d_lo = bid * 14; if (d_lo > Dn) d_lo = Dn;
    int d_hi = d_lo + 14; if (d_hi > Dn) d_hi = Dn;
    const int nrows = d_hi - d_lo;
    unsigned gen = 0;

    for (int k = 0; k < Kn; ++k) {
        const int pin = k & 1, pout = pin ^ 1;

        // ---------------- P1 ----------------
        float s = 0.f, c1k1 = 0.f;
        if (k > 0) {
            s = rsqrtf(g_dn2[pin]);
            c1k1 = s * g_uv[pin];
            for (int j = tid; j < k - 1; j += 256) {
                sc3s[j] = g_c3[pin][j] * s;
                sc1[j]  = g_c1[pin][j];
            }
        }
        if (bid == 0) {
            for (int j = tid; j < Kn; j += 256) {
                g_c3[pout][j] = 0.f;
                g_c1[pout][j] = 0.f;
                g_g[j] = 0.f;
            }
            if (tid == 0) { g_dn2[pout] = 0.f; g_uv[pout] = 0.f; }
        }
        __syncthreads();

        if (k == 0) {
            for (int d = d_lo + tid; d < d_hi; d += 256)
                g_a[d] = g_Vt[d];
        } else {
            for (int dd = wid; dd < nrows; dd += 8) {
                int d = d_lo + dd;
                float u_d = g_u[d];
                const float* wrow = &g_WT[(size_t)d * Kn];
                float sum1 = 0.f, sum2 = 0.f;
                for (int j = lane; j < k - 1; j += 32) {
                    float wj = wrow[j];
                    sum1 += sc3s[j] * wj;
                    sum2 += sc1[j] * wj;
                }
                #pragma unroll
                for (int o = 16; o; o >>= 1) {
                    sum1 += __shfl_down_sync(~0u, sum1, o);
                    sum2 += __shfl_down_sync(~0u, sum2, o);
                }
                if (lane == 0) {
                    float vn_d = s * u_d;
                    float w_d = vn_d - sum1;
                    g_VnT[(size_t)d * Kn + (k - 1)] = vn_d;
                    g_WT[(size_t)d * Kn + (k - 1)] = w_d;
                    g_a[d] = g_Vt[(size_t)k * Dn + d] - sum2 - c1k1 * w_d;
                }
            }
        }
        gbar(gen);

        // ---------------- P2: b = C a, g_j partials ----------------
        for (int i = tid; i < Dn / 4; i += 256)
            ((float4*)s_a)[i] = ((const float4*)g_a)[i];
        __syncthreads();
        for (int dd = wid; dd < nrows; dd += 8) {
            int d = d_lo + dd;
            const float4* crow = (const float4*)&g_C[(size_t)d * Dn];
            float sum = 0.f;
            for (int t = lane; t < Dn / 4; t += 32) {
                float4 c4 = crow[t];
                float4 a4 = ((const float4*)s_a)[t];
                sum += c4.x * a4.x + c4.y * a4.y + c4.z * a4.z + c4.w * a4.w;
            }
            #pragma unroll
            for (int o = 16; o; o >>= 1) sum += __shfl_down_sync(~0u, sum, o);
            if (lane == 0) s_b[dd] = sum;
        }
        __syncthreads();
        if (tid < k && nrows > 0) {
            float accg = 0.f;
            for (int dd = 0; dd < nrows; ++dd)
                accg += g_WT[(size_t)(d_lo + dd) * Kn + tid] * s_b[dd];
            atomicAdd(&g_g[tid], accg);
        }
        gbar(gen);

        // ---------------- P3: u update + next-step dots ----------------
        const float hh = 0.5f / g_d0[k];
        for (int j = tid; j < k; j += 256) s_g[j] = g_g[j];
        __syncthreads();
        for (int dd = wid; dd < nrows; dd += 8) {
            int d = d_lo + dd;
            const float* vrow = &g_VnT[(size_t)d * Kn];
            float sumg = 0.f;
            for (int j = lane; j < k; j += 32) sumg += s_g[j] * vrow[j];
            #pragma unroll
            for (int o = 16; o; o >>= 1) sumg += __shfl_down_sync(~0u, sumg, o);
            if (lane == 0) {
                float u_d = 0.5f * g_Vt[(size_t)k * Dn + d] + hh * (s_b[dd] - sumg);
                g_u[d] = u_d;
                s_u[dd] = u_d;
                s_vk1[dd] = (k + 1 < Kn) ? g_Vt[(size_t)(k + 1) * Dn + d] : 0.f;
            }
        }
        __syncthreads();
        if (tid < k && nrows > 0) {
            float a3 = 0.f, a1 = 0.f;
            for (int dd = 0; dd < nrows; ++dd) {
                float vv = g_VnT[(size_t)(d_lo + dd) * Kn + tid];
                a3 += vv * s_u[dd];
                a1 += vv * s_vk1[dd];
            }
            atomicAdd(&g_c3[pout][tid], a3);
            atomicAdd(&g_c1[pout][tid], a1);
        }
        if (tid == 0 && nrows > 0) {
            float d2 = 0.f, uvv = 0.f;
            for (int dd = 0; dd < nrows; ++dd) {
                d2  += s_u[dd] * s_u[dd];
                uvv += s_u[dd] * s_vk1[dd];
            }
            atomicAdd(&g_dn2[pout], d2);
            atomicAdd(&g_uv[pout], uvv);
        }
        gbar(gen);
    }

    // epilogue: write vn_{K-1}
    {
        const int plast = ((Kn - 1) & 1) ^ 1;
        float s = rsqrtf(g_dn2[plast]);
        for (int d = d_lo + tid; d < d_hi; d += 256)
            g_VnT[(size_t)d * Kn + (Kn - 1)] = s * g_u[d];
    }

    // reset barrier state for the next graph replay (only globally-last block)
    __syncthreads();
    if (tid == 0) {
        __threadfence();
        if (atomicAdd(&g_done, 1u) == (unsigned)(gridDim.x - 1)) {
            g_done = 0u;
            g_barcnt = 0u;
            atomicExch(&g_bargen, 0u);
            __threadfence();
        }
    }
}

// ---------------- out = x @ VnT  ([8192,2048] x [2048,256]) ----------------
__global__ void __launch_bounds__(256) gemmOut_kernel(const float* __restrict__ x,
                                                      float* __restrict__ out) {
    __shared__ __align__(16) float As[16][132];  // transposed x tile, padded
    __shared__ __align__(16) float Bs[16][64];

    const int br = blockIdx.x >> 2;   // 64 row tiles of 128
    const int bc = blockIdx.x & 3;    // 4 col tiles of 64
    const int tid = threadIdx.x;
    const int ty = tid >> 4, tx = tid & 15;
    const int n0 = br * 128;

    float acc[8][4];
    #pragma unroll
    for (int p = 0; p < 8; ++p)
        #pragma unroll
        for (int q = 0; q < 4; ++q) acc[p][q] = 0.f;

    for (int dchunk = 0; dchunk < Dn; dchunk += 16) {
        #pragma unroll
        for (int it = 0; it < 2; ++it) {
            int idx4 = tid + it * 256;        // 0..511
            int r = idx4 >> 2;                // 0..127
            int c4 = idx4 & 3;                // 0..3
            float4 v = *(const float4*)(x + (size_t)(n0 + r) * Dn + dchunk + c4 * 4);
            As[c4 * 4 + 0][r] = v.x;
            As[c4 * 4 + 1][r] = v.y;
            As[c4 * 4 + 2][r] = v.z;
            As[c4 * 4 + 3][r] = v.w;
        }
        {
            int kk = tid >> 4;   // 0..15
            int c4 = tid & 15;   // 0..15
            ((float4*)&Bs[kk][0])[c4] =
                *(const float4*)(&g_VnT[(size_t)(dchunk + kk) * Kn + bc * 64 + c4 * 4]);
        }
        __syncthreads();
        #pragma unroll
        for (int kk = 0; kk < 16; ++kk) {
            float a8[8], b4[4];
            *(float4*)&a8[0] = *(const float4*)&As[kk][ty * 8];
            *(float4*)&a8[4] = *(const float4*)&As[kk][ty * 8 + 4];
            *(float4*)&b4[0] = *(const float4*)&Bs[kk][tx * 4];
            #pragma unroll
            for (int p = 0; p < 8; ++p)
                #pragma unroll
                for (int q = 0; q < 4; ++q) acc[p][q] += a8[p] * b4[q];
        }
        __syncthreads();
    }

    #pragma unroll
    for (int p = 0; p < 8; ++p)
        *(float4*)(out + (size_t)(n0 + ty * 8 + p) * Kn + bc * 64 + tx * 4) =
            make_float4(acc[p][0], acc[p][1], acc[p][2], acc[p][3]);
}

// ---------------- launch ----------------
extern "C" void kernel_launch(void* const* d_in, const int* in_sizes, int n_in,
                              void* d_out, int out_size) {
    const float* x  = (const float*)d_in[0];
    const float* V0 = (const float*)d_in[1];
    // defensive: identify by size (x has N*D elements, V0 has D*K)
    if (n_in >= 2 && in_sizes[0] == Dn * Kn && in_sizes[1] == Nn * Dn) {
        const float* t = x; x = V0; V0 = t;
    }
    float* out = (float*)d_out;

    prep_kernel<<<Kn, 256>>>(V0);
    gemmC_kernel<<<136, 256>>>(x);
    solve_kernel<<<NBLK, 256>>>();
    gemmOut_kernel<<<256, 256>>>(x, out);
}

// round 3
// speedup vs baseline: 1.2526x; 1.2526x over previous
#include <cuda_runtime.h>
#include <math.h>

#define Nn 8192
#define Dn 2048
#define Kn 256
#define NBLK 148
#define ROWS_PB 14            // 148 * 14 = 2072 >= 2048

// ---------------- device scratch (static: no allocation allowed) ----------------
__device__ float g_C[(size_t)Dn * Dn];     // 16 MB  C = x^T x
__device__ float g_Vt[(size_t)Kn * Dn];    // Vt[k][d] = V0[d][k]
__device__ float g_WT[(size_t)Dn * Kn];    // WT[d][j] = w_j[d]
__device__ float g_VnT[(size_t)Dn * Kn];   // VnT[d][j] = vn_j[d]
__device__ float g_a[Dn];
__device__ float g_u[Dn];
__device__ float g_c1[2][Kn];              // vn_j . v_{k}   (double buffered)
__device__ float g_c3[2][Kn];              // vn_j . u       (double buffered)
__device__ float g_g[Kn];                  // w_j . b
__device__ float g_d0[Kn];
__device__ float g_dn2[2];
__device__ float g_uv[2];
__device__ unsigned g_barcnt;              // monotonic barrier counter
__device__ unsigned g_done;

// ---------------- grid barrier: monotonic red.release + acquire poll ----------
// All NBLK CTAs are co-resident (grid <= #SMs, 1 CTA/SM), so spin is safe.
__device__ __forceinline__ void gbar(unsigned& gen) {
    gen += gridDim.x;
    __syncthreads();
    if (threadIdx.x == 0) {
        asm volatile("red.release.gpu.global.add.u32 [%0], 1;"
                     :: "l"(&g_barcnt) : "memory");
        unsigned v;
        do {
            asm volatile("ld.acquire.gpu.global.u32 %0, [%1];"
                         : "=r"(v) : "l"(&g_barcnt) : "memory");
        } while ((int)(v - gen) < 0);
    }
    __syncthreads();
}

// ---------------- prep: transpose V0 -> Vt, per-column norms d0 ----------------
__global__ void __launch_bounds__(256) prep_kernel(const float* __restrict__ V0) {
    __shared__ float sb[8];
    int k = blockIdx.x;
    float s = 0.f;
    for (int d = threadIdx.x; d < Dn; d += 256) {
        float v = V0[(size_t)d * Kn + k];
        g_Vt[(size_t)k * Dn + d] = v;
        s += v * v;
    }
    #pragma unroll
    for (int o = 16; o; o >>= 1) s += __shfl_down_sync(~0u, s, o);
    if ((threadIdx.x & 31) == 0) sb[threadIdx.x >> 5] = s;
    __syncthreads();
    if (threadIdx.x == 0) {
        float t = 0.f;
        #pragma unroll
        for (int w = 0; w < 8; ++w) t += sb[w];
        g_d0[k] = sqrtf(t);
    }
}

// ---------------- C = x^T x (symmetric: 136 upper-tri 128x128 tile pairs) ------
__global__ void __launch_bounds__(256) gemmC_kernel(const float* __restrict__ x) {
    __shared__ __align__(16) float As[16][128];
    __shared__ __align__(16) float Bs[16][128];

    int rem = blockIdx.x, bi = 0, width = 16;
    while (rem >= width) { rem -= width; ++bi; --width; }
    int bj = bi + rem;

    const int tid = threadIdx.x;
    const int ty = tid >> 4, tx = tid & 15;
    float acc[8][8];
    #pragma unroll
    for (int p = 0; p < 8; ++p)
        #pragma unroll
        for (int q = 0; q < 8; ++q) acc[p][q] = 0.f;

    for (int n0 = 0; n0 < Nn; n0 += 16) {
        #pragma unroll
        for (int it = 0; it < 2; ++it) {
            int idx = tid + it * 256;
            int r = idx >> 5;
            int c4 = idx & 31;
            const float4* xr = (const float4*)(x + (size_t)(n0 + r) * Dn);
            ((float4*)&As[r][0])[c4] = xr[bi * 32 + c4];
            ((float4*)&Bs[r][0])[c4] = xr[bj * 32 + c4];
        }
        __syncthreads();
        #pragma unroll
        for (int kk = 0; kk < 16; ++kk) {
            float a8[8], b8[8];
            *(float4*)&a8[0] = *(const float4*)&As[kk][ty * 8];
            *(float4*)&a8[4] = *(const float4*)&As[kk][ty * 8 + 4];
            *(float4*)&b8[0] = *(const float4*)&Bs[kk][tx * 8];
            *(float4*)&b8[4] = *(const float4*)&Bs[kk][tx * 8 + 4];
            #pragma unroll
            for (int p = 0; p < 8; ++p)
                #pragma unroll
                for (int q = 0; q < 8; ++q) acc[p][q] += a8[p] * b8[q];
        }
        __syncthreads();
    }

    int gi = bi * 128 + ty * 8;
    int gj = bj * 128 + tx * 8;
    #pragma unroll
    for (int p = 0; p < 8; ++p) {
        float* dst = g_C + (size_t)(gi + p) * Dn + gj;
        *(float4*)(dst)     = make_float4(acc[p][0], acc[p][1], acc[p][2], acc[p][3]);
        *(float4*)(dst + 4) = make_float4(acc[p][4], acc[p][5], acc[p][6], acc[p][7]);
    }
    if (bi != bj) {
        #pragma unroll
        for (int q = 0; q < 8; ++q) {
            float* dst = g_C + (size_t)(gj + q) * Dn + gi;
            *(float4*)(dst)     = make_float4(acc[0][q], acc[1][q], acc[2][q], acc[3][q]);
            *(float4*)(dst + 4) = make_float4(acc[4][q], acc[5][q], acc[6][q], acc[7][q]);
        }
    }
}

// ---------------- persistent sequential CCIPCA solve ----------------
// Block's C-row slice (14 rows x 8KB = 112KB) lives in SMEM for all 256 steps.
// Step k, 3 grid barriers:
//  P1: vn_{k-1} = s*u ; w_{k-1} = vn_{k-1} - sum_{j<k-1} (s*c3_j) w_j ;
//      a = v_k - sum_{j<k-1} c1_j w_j - (s*uv) w_{k-1}
//  P2: b = C a (SMEM rows) ; partial g_j += w_j . b (atomics)
//  P3: u = 0.5 v_k + (0.5/d0_k)(b - sum_j g_j vn_j) ;
//      next-step partial dots: c3_j += vn_j.u ; c1_j += vn_j.v_{k+1} ;
//      dn2 += u^2 ; uv += u.v_{k+1}
__global__ void __launch_bounds__(256) solve_kernel() {
    extern __shared__ __align__(16) float s_C[];   // ROWS_PB * Dn floats (dynamic)
    __shared__ __align__(16) float s_a[Dn];        // 8 KB
    __shared__ float sc3s[Kn], sc1[Kn], s_g[Kn];
    __shared__ float s_b[16], s_u[16], s_vk1[16];

    const int tid = threadIdx.x;
    const int bid = blockIdx.x;
    const int wid = tid >> 5, lane = tid & 31;
    int d_lo = bid * ROWS_PB; if (d_lo > Dn) d_lo = Dn;
    int d_hi = d_lo + ROWS_PB; if (d_hi > Dn) d_hi = Dn;
    const int nrows = d_hi - d_lo;
    unsigned gen = 0;

    // --- cache this block's C rows in SMEM (C is constant across all steps) ---
    {
        const float4* src = (const float4*)&g_C[(size_t)d_lo * Dn];
        float4* dst = (float4*)s_C;
        for (int i = tid; i < nrows * (Dn / 4); i += 256) dst[i] = src[i];
    }
    __syncthreads();

    for (int k = 0; k < Kn; ++k) {
        const int pin = k & 1, pout = pin ^ 1;

        // ---------------- P1 ----------------
        float s = 0.f, c1k1 = 0.f;
        if (k > 0) {
            s = rsqrtf(g_dn2[pin]);
            c1k1 = s * g_uv[pin];
            for (int j = tid; j < k - 1; j += 256) {
                sc3s[j] = g_c3[pin][j] * s;
                sc1[j]  = g_c1[pin][j];
            }
        }
        if (bid == 0) {
            for (int j = tid; j < Kn; j += 256) {
                g_c3[pout][j] = 0.f;
                g_c1[pout][j] = 0.f;
                g_g[j] = 0.f;
            }
            if (tid == 0) { g_dn2[pout] = 0.f; g_uv[pout] = 0.f; }
        }
        __syncthreads();

        if (k == 0) {
            for (int d = d_lo + tid; d < d_hi; d += 256)
                g_a[d] = g_Vt[d];
        } else {
            for (int dd = wid; dd < nrows; dd += 8) {
                int d = d_lo + dd;
                float u_d = g_u[d];
                const float* wrow = &g_WT[(size_t)d * Kn];
                float sum1 = 0.f, sum2 = 0.f;
                for (int j = lane; j < k - 1; j += 32) {
                    float wj = wrow[j];
                    sum1 += sc3s[j] * wj;
                    sum2 += sc1[j] * wj;
                }
                #pragma unroll
                for (int o = 16; o; o >>= 1) {
                    sum1 += __shfl_down_sync(~0u, sum1, o);
                    sum2 += __shfl_down_sync(~0u, sum2, o);
                }
                if (lane == 0) {
                    float vn_d = s * u_d;
                    float w_d = vn_d - sum1;
                    g_VnT[(size_t)d * Kn + (k - 1)] = vn_d;
                    g_WT[(size_t)d * Kn + (k - 1)] = w_d;
                    g_a[d] = g_Vt[(size_t)k * Dn + d] - sum2 - c1k1 * w_d;
                }
            }
        }
        gbar(gen);

        // ---------------- P2: b = C a (SMEM), g_j partials ----------------
        for (int i = tid; i < Dn / 4; i += 256)
            ((float4*)s_a)[i] = ((const float4*)g_a)[i];
        __syncthreads();
        for (int dd = wid; dd < nrows; dd += 8) {
            const float4* crow = (const float4*)&s_C[dd * Dn];
            float sum = 0.f;
            #pragma unroll 4
            for (int t = lane; t < Dn / 4; t += 32) {
                float4 c4 = crow[t];
                float4 a4 = ((const float4*)s_a)[t];
                sum += c4.x * a4.x + c4.y * a4.y + c4.z * a4.z + c4.w * a4.w;
            }
            #pragma unroll
            for (int o = 16; o; o >>= 1) sum += __shfl_down_sync(~0u, sum, o);
            if (lane == 0) s_b[dd] = sum;
        }
        __syncthreads();
        if (tid < k && nrows > 0) {
            float accg = 0.f;
            for (int dd = 0; dd < nrows; ++dd)
                accg += g_WT[(size_t)(d_lo + dd) * Kn + tid] * s_b[dd];
            atomicAdd(&g_g[tid], accg);
        }
        gbar(gen);

        // ---------------- P3: u update + next-step dots ----------------
        const float hh = 0.5f / g_d0[k];
        for (int j = tid; j < k; j += 256) s_g[j] = g_g[j];
        __syncthreads();
        for (int dd = wid; dd < nrows; dd += 8) {
            int d = d_lo + dd;
            const float* vrow = &g_VnT[(size_t)d * Kn];
            float sumg = 0.f;
            for (int j = lane; j < k; j += 32) sumg += s_g[j] * vrow[j];
            #pragma unroll
            for (int o = 16; o; o >>= 1) sumg += __shfl_down_sync(~0u, sumg, o);
            if (lane == 0) {
                float u_d = 0.5f * g_Vt[(size_t)k * Dn + d] + hh * (s_b[dd] - sumg);
                g_u[d] = u_d;
                s_u[dd] = u_d;
                s_vk1[dd] = (k + 1 < Kn) ? g_Vt[(size_t)(k + 1) * Dn + d] : 0.f;
            }
        }
        __syncthreads();
        if (tid < k && nrows > 0) {
            float a3 = 0.f, a1 = 0.f;
            for (int dd = 0; dd < nrows; ++dd) {
                float vv = g_VnT[(size_t)(d_lo + dd) * Kn + tid];
                a3 += vv * s_u[dd];
                a1 += vv * s_vk1[dd];
            }
            atomicAdd(&g_c3[pout][tid], a3);
            atomicAdd(&g_c1[pout][tid], a1);
        }
        if (tid == 0 && nrows > 0) {
            float d2 = 0.f, uvv = 0.f;
            for (int dd = 0; dd < nrows; ++dd) {
                d2  += s_u[dd] * s_u[dd];
                uvv += s_u[dd] * s_vk1[dd];
            }
            atomicAdd(&g_dn2[pout], d2);
            atomicAdd(&g_uv[pout], uvv);
        }
        gbar(gen);
    }

    // epilogue: write vn_{K-1}
    {
        const int plast = ((Kn - 1) & 1) ^ 1;
        float s = rsqrtf(g_dn2[plast]);
        for (int d = d_lo + tid; d < d_hi; d += 256)
            g_VnT[(size_t)d * Kn + (Kn - 1)] = s * g_u[d];
    }

    // reset barrier counter for the next graph replay (globally-last block)
    __syncthreads();
    if (tid == 0) {
        __threadfence();
        if (atomicAdd(&g_done, 1u) == (unsigned)(gridDim.x - 1)) {
            g_done = 0u;
            g_barcnt = 0u;
            __threadfence();
        }
    }
}

// ---------------- out = x @ VnT  ([8192,2048] x [2048,256]) ----------------
__global__ void __launch_bounds__(256) gemmOut_kernel(const float* __restrict__ x,
                                                      float* __restrict__ out) {
    __shared__ __align__(16) float As[16][132];
    __shared__ __align__(16) float Bs[16][64];

    const int br = blockIdx.x >> 2;
    const int bc = blockIdx.x & 3;
    const int tid = threadIdx.x;
    const int ty = tid >> 4, tx = tid & 15;
    const int n0 = br * 128;

    float acc[8][4];
    #pragma unroll
    for (int p = 0; p < 8; ++p)
        #pragma unroll
        for (int q = 0; q < 4; ++q) acc[p][q] = 0.f;

    for (int dchunk = 0; dchunk < Dn; dchunk += 16) {
        #pragma unroll
        for (int it = 0; it < 2; ++it) {
            int idx4 = tid + it * 256;
            int r = idx4 >> 2;
            int c4 = idx4 & 3;
            float4 v = *(const float4*)(x + (size_t)(n0 + r) * Dn + dchunk + c4 * 4);
            As[c4 * 4 + 0][r] = v.x;
            As[c4 * 4 + 1][r] = v.y;
            As[c4 * 4 + 2][r] = v.z;
            As[c4 * 4 + 3][r] = v.w;
        }
        {
            int kk = tid >> 4;
            int c4 = tid & 15;
            ((float4*)&Bs[kk][0])[c4] =
                *(const float4*)(&g_VnT[(size_t)(dchunk + kk) * Kn + bc * 64 + c4 * 4]);
        }
        __syncthreads();
        #pragma unroll
        for (int kk = 0; kk < 16; ++kk) {
            float a8[8], b4[4];
            *(float4*)&a8[0] = *(const float4*)&As[kk][ty * 8];
            *(float4*)&a8[4] = *(const float4*)&As[kk][ty * 8 + 4];
            *(float4*)&b4[0] = *(const float4*)&Bs[kk][tx * 4];
            #pragma unroll
            for (int p = 0; p < 8; ++p)
                #pragma unroll
                for (int q = 0; q < 4; ++q) acc[p][q] += a8[p] * b4[q];
        }
        __syncthreads();
    }

    #pragma unroll
    for (int p = 0; p < 8; ++p)
        *(float4*)(out + (size_t)(n0 + ty * 8 + p) * Kn + bc * 64 + tx * 4) =
            make_float4(acc[p][0], acc[p][1], acc[p][2], acc[p][3]);
}

// ---------------- launch ----------------
extern "C" void kernel_launch(void* const* d_in, const int* in_sizes, int n_in,
                              void* d_out, int out_size) {
    const float* x  = (const float*)d_in[0];
    const float* V0 = (const float*)d_in[1];
    if (n_in >= 2 && in_sizes[0] == Dn * Kn && in_sizes[1] == Nn * Dn) {
        const float* t = x; x = V0; V0 = t;
    }
    float* out = (float*)d_out;

    static int smem_set = 0;
    const int dyn_smem = ROWS_PB * Dn * (int)sizeof(float);  // 114688 B
    if (!smem_set) {
        cudaFuncSetAttribute(solve_kernel,
                             cudaFuncAttributeMaxDynamicSharedMemorySize, dyn_smem);
        smem_set = 1;
    }

    prep_kernel<<<Kn, 256>>>(V0);
    gemmC_kernel<<<136, 256>>>(x);
    solve_kernel<<<NBLK, 256, dyn_smem>>>();
    gemmOut_kernel<<<256, 256>>>(x, out);
}

// round 4
// speedup vs baseline: 1.5438x; 1.2325x over previous
#include <cuda_runtime.h>
#include <math.h>

#define Nn 8192
#define Dn 2048
#define Kn 256
#define NBLK 148
#define ROWS_PB 14            // 148 * 14 = 2072 >= 2048

typedef unsigned long long ull;

// ---------------- f32x2 packed FMA helpers (Blackwell FFMA2) ----------------
__device__ __forceinline__ ull splat2(float s) {
    ull d;
    asm("mov.b64 %0, {%1, %1};" : "=l"(d) : "r"(__float_as_uint(s)));
    return d;
}
__device__ __forceinline__ void fma2(ull& d, ull a, ull b) {
    asm("fma.rn.f32x2 %0, %1, %2, %0;" : "+l"(d) : "l"(a), "l"(b));
}

// ---------------- device scratch (static: no allocation allowed) ----------------
__device__ float g_C[(size_t)Dn * Dn];     // 16 MB  C = x^T x
__device__ float g_Vt[(size_t)Kn * Dn];    // Vt[k][d] = V0[d][k]
__device__ float g_VnT[(size_t)Dn * Kn];   // VnT[d][j] = vn_j[d] (for gemmOut)
__device__ float g_a[Dn];
__device__ float g_c1[2][Kn];              // vn_j . v_{k}   (double buffered)
__device__ float g_c3[2][Kn];              // vn_j . u       (double buffered)
__device__ float g_g[Kn];                  // w_j . b
__device__ float g_d0[Kn];
__device__ float g_dn2[2];
__device__ float g_uv[2];
__device__ unsigned g_barcnt;              // monotonic barrier counter
__device__ unsigned g_done;

// ---------------- grid barrier: monotonic red.release + acquire poll ----------
__device__ __forceinline__ void gbar(unsigned& gen) {
    gen += gridDim.x;
    __syncthreads();
    if (threadIdx.x == 0) {
        asm volatile("red.release.gpu.global.add.u32 [%0], 1;"
                     :: "l"(&g_barcnt) : "memory");
        unsigned v;
        do {
            asm volatile("ld.acquire.gpu.global.u32 %0, [%1];"
                         : "=r"(v) : "l"(&g_barcnt) : "memory");
        } while ((int)(v - gen) < 0);
    }
    __syncthreads();
}

// ---------------- prep: transpose V0 -> Vt, per-column norms d0 ----------------
__global__ void __launch_bounds__(256) prep_kernel(const float* __restrict__ V0) {
    __shared__ float sb[8];
    int k = blockIdx.x;
    float s = 0.f;
    for (int d = threadIdx.x; d < Dn; d += 256) {
        float v = V0[(size_t)d * Kn + k];
        g_Vt[(size_t)k * Dn + d] = v;
        s += v * v;
    }
    #pragma unroll
    for (int o = 16; o; o >>= 1) s += __shfl_down_sync(~0u, s, o);
    if ((threadIdx.x & 31) == 0) sb[threadIdx.x >> 5] = s;
    __syncthreads();
    if (threadIdx.x == 0) {
        float t = 0.f;
        #pragma unroll
        for (int w = 0; w < 8; ++w) t += sb[w];
        g_d0[k] = sqrtf(t);
    }
}

// ---------------- C = x^T x (symmetric: 136 upper-tri 128x128 tile pairs) ------
__global__ void __launch_bounds__(256) gemmC_kernel(const float* __restrict__ x) {
    __shared__ __align__(16) float As[16][128];
    __shared__ __align__(16) float Bs[16][128];

    int rem = blockIdx.x, bi = 0, width = 16;
    while (rem >= width) { rem -= width; ++bi; --width; }
    int bj = bi + rem;

    const int tid = threadIdx.x;
    const int ty = tid >> 4, tx = tid & 15;
    ull acc2[8][4];
    const ull z = splat2(0.f);
    #pragma unroll
    for (int p = 0; p < 8; ++p)
        #pragma unroll
        for (int q = 0; q < 4; ++q) acc2[p][q] = z;

    for (int n0 = 0; n0 < Nn; n0 += 16) {
        #pragma unroll
        for (int it = 0; it < 2; ++it) {
            int idx = tid + it * 256;
            int r = idx >> 5;
            int c4 = idx & 31;
            const float4* xr = (const float4*)(x + (size_t)(n0 + r) * Dn);
            ((float4*)&As[r][0])[c4] = xr[bi * 32 + c4];
            ((float4*)&Bs[r][0])[c4] = xr[bj * 32 + c4];
        }
        __syncthreads();
        #pragma unroll
        for (int kk = 0; kk < 16; ++kk) {
            float a8[8];
            *(float4*)&a8[0] = *(const float4*)&As[kk][ty * 8];
            *(float4*)&a8[4] = *(const float4*)&As[kk][ty * 8 + 4];
            const ull* bp = (const ull*)&Bs[kk][tx * 8];
            ull b2[4];
            #pragma unroll
            for (int q = 0; q < 4; ++q) b2[q] = bp[q];
            #pragma unroll
            for (int p = 0; p < 8; ++p) {
                ull ap = splat2(a8[p]);
                #pragma unroll
                for (int q = 0; q < 4; ++q) fma2(acc2[p][q], ap, b2[q]);
            }
        }
        __syncthreads();
    }

    int gi = bi * 128 + ty * 8;
    int gj = bj * 128 + tx * 8;
    float acc[8][8];
    #pragma unroll
    for (int p = 0; p < 8; ++p)
        #pragma unroll
        for (int q = 0; q < 4; ++q) {
            float2 v = *(float2*)&acc2[p][q];
            acc[p][2 * q] = v.x;
            acc[p][2 * q + 1] = v.y;
        }
    #pragma unroll
    for (int p = 0; p < 8; ++p) {
        float* dst = g_C + (size_t)(gi + p) * Dn + gj;
        *(float4*)(dst)     = make_float4(acc[p][0], acc[p][1], acc[p][2], acc[p][3]);
        *(float4*)(dst + 4) = make_float4(acc[p][4], acc[p][5], acc[p][6], acc[p][7]);
    }
    if (bi != bj) {
        #pragma unroll
        for (int q = 0; q < 8; ++q) {
            float* dst = g_C + (size_t)(gj + q) * Dn + gi;
            *(float4*)(dst)     = make_float4(acc[0][q], acc[1][q], acc[2][q], acc[3][q]);
            *(float4*)(dst + 4) = make_float4(acc[4][q], acc[5][q], acc[6][q], acc[7][q]);
        }
    }
}

// ---------------- persistent sequential CCIPCA solve ----------------
// Per-block SMEM residency: C slice (112 KB), WT slice (14 KB), VnT slice (14 KB).
// Step k, 3 grid barriers:
//  P1: vn_{k-1} = s*u ; w_{k-1} = vn_{k-1} - sum_{j<k-1} (s*c3_j) w_j ;
//      a = v_k - sum_{j<k-1} c1_j w_j - (s*uv) w_{k-1}
//  P2: b = C a (SMEM) ; partial g_j += w_j . b (atomics)
//  P3: u = 0.5 v_k + (0.5/d0_k)(b - sum_j g_j vn_j) ;
//      next-step partial dots: c3_j += vn_j.u ; c1_j += vn_j.v_{k+1} ;
//      dn2 += u^2 ; uv += u.v_{k+1}
__global__ void __launch_bounds__(256) solve_kernel() {
    extern __shared__ __align__(16) float s_dyn[];
    float* s_C   = s_dyn;                                  // ROWS_PB*Dn
    float* s_WT  = s_dyn + ROWS_PB * Dn;                   // ROWS_PB*Kn
    float* s_VnT = s_dyn + ROWS_PB * Dn + ROWS_PB * Kn;    // ROWS_PB*Kn
    __shared__ __align__(16) float s_a[Dn];                // 8 KB
    __shared__ float sc3s[Kn], sc1[Kn], s_g[Kn];
    __shared__ float s_b[16], s_u[16], s_vk1[16];

    const int tid = threadIdx.x;
    const int bid = blockIdx.x;
    const int wid = tid >> 5, lane = tid & 31;
    int d_lo = bid * ROWS_PB; if (d_lo > Dn) d_lo = Dn;
    int d_hi = d_lo + ROWS_PB; if (d_hi > Dn) d_hi = Dn;
    const int nrows = d_hi - d_lo;
    unsigned gen = 0;

    // --- cache this block's C rows in SMEM (constant across all steps) ---
    {
        const float4* src = (const float4*)&g_C[(size_t)d_lo * Dn];
        float4* dst = (float4*)s_C;
        for (int i = tid; i < nrows * (Dn / 4); i += 256) dst[i] = src[i];
    }
    __syncthreads();

    for (int k = 0; k < Kn; ++k) {
        const int pin = k & 1, pout = pin ^ 1;

        // ---------------- P1 ----------------
        float s = 0.f, c1k1 = 0.f;
        if (k > 0) {
            s = rsqrtf(g_dn2[pin]);
            c1k1 = s * g_uv[pin];
            for (int j = tid; j < k - 1; j += 256) {
                sc3s[j] = g_c3[pin][j] * s;
                sc1[j]  = g_c1[pin][j];
            }
        }
        if (bid == 0) {
            for (int j = tid; j < Kn; j += 256) {
                g_c3[pout][j] = 0.f;
                g_c1[pout][j] = 0.f;
                g_g[j] = 0.f;
            }
            if (tid == 0) { g_dn2[pout] = 0.f; g_uv[pout] = 0.f; }
        }
        __syncthreads();

        if (k == 0) {
            for (int d = d_lo + tid; d < d_hi; d += 256)
                g_a[d] = g_Vt[d];
        } else {
            for (int dd = wid; dd < nrows; dd += 8) {
                int d = d_lo + dd;
                float u_d = s_u[dd];
                const float* wrow = &s_WT[dd * Kn];
                float sum1 = 0.f, sum2 = 0.f;
                #pragma unroll 4
                for (int j = lane; j < k - 1; j += 32) {
                    float wj = wrow[j];
                    sum1 += sc3s[j] * wj;
                    sum2 += sc1[j] * wj;
                }
                #pragma unroll
                for (int o = 16; o; o >>= 1) {
                    sum1 += __shfl_down_sync(~0u, sum1, o);
                    sum2 += __shfl_down_sync(~0u, sum2, o);
                }
                if (lane == 0) {
                    float vn_d = s * u_d;
                    float w_d = vn_d - sum1;
                    s_VnT[dd * Kn + (k - 1)] = vn_d;
                    g_VnT[(size_t)d * Kn + (k - 1)] = vn_d;  // for gemmOut
                    s_WT[dd * Kn + (k - 1)] = w_d;
                    g_a[d] = g_Vt[(size_t)k * Dn + d] - sum2 - c1k1 * w_d;
                }
            }
        }
        gbar(gen);

        // ---------------- P2: b = C a (SMEM), g_j partials ----------------
        for (int i = tid; i < Dn / 4; i += 256)
            ((float4*)s_a)[i] = ((const float4*)g_a)[i];
        __syncthreads();
        for (int dd = wid; dd < nrows; dd += 8) {
            const float4* crow = (const float4*)&s_C[dd * Dn];
            float sum = 0.f;
            #pragma unroll 4
            for (int t = lane; t < Dn / 4; t += 32) {
                float4 c4 = crow[t];
                float4 a4 = ((const float4*)s_a)[t];
                sum += c4.x * a4.x + c4.y * a4.y + c4.z * a4.z + c4.w * a4.w;
            }
            #pragma unroll
            for (int o = 16; o; o >>= 1) sum += __shfl_down_sync(~0u, sum, o);
            if (lane == 0) s_b[dd] = sum;
        }
        __syncthreads();
        if (tid < k && nrows > 0) {
            float accg = 0.f;
            #pragma unroll 7
            for (int dd = 0; dd < nrows; ++dd)
                accg += s_WT[dd * Kn + tid] * s_b[dd];
            atomicAdd(&g_g[tid], accg);
        }
        gbar(gen);

        // ---------------- P3: u update + next-step dots ----------------
        const float hh = 0.5f / g_d0[k];
        for (int j = tid; j < k; j += 256) s_g[j] = g_g[j];
        __syncthreads();
        for (int dd = wid; dd < nrows; dd += 8) {
            int d = d_lo + dd;
            const float* vrow = &s_VnT[dd * Kn];
            float sumg = 0.f;
            #pragma unroll 4
            for (int j = lane; j < k; j += 32) sumg += s_g[j] * vrow[j];
            #pragma unroll
            for (int o = 16; o; o >>= 1) sumg += __shfl_down_sync(~0u, sumg, o);
            if (lane == 0) {
                float u_d = 0.5f * g_Vt[(size_t)k * Dn + d] + hh * (s_b[dd] - sumg);
                s_u[dd] = u_d;
                s_vk1[dd] = (k + 1 < Kn) ? g_Vt[(size_t)(k + 1) * Dn + d] : 0.f;
            }
        }
        __syncthreads();
        if (tid < k && nrows > 0) {
            float a3 = 0.f, a1 = 0.f;
            #pragma unroll 7
            for (int dd = 0; dd < nrows; ++dd) {
                float vv = s_VnT[dd * Kn + tid];
                a3 += vv * s_u[dd];
                a1 += vv * s_vk1[dd];
            }
            atomicAdd(&g_c3[pout][tid], a3);
            atomicAdd(&g_c1[pout][tid], a1);
        }
        if (tid == 0 && nrows > 0) {
            float d2 = 0.f, uvv = 0.f;
            #pragma unroll 7
            for (int dd = 0; dd < nrows; ++dd) {
                d2  += s_u[dd] * s_u[dd];
                uvv += s_u[dd] * s_vk1[dd];
            }
            atomicAdd(&g_dn2[pout], d2);
            atomicAdd(&g_uv[pout], uvv);
        }
        gbar(gen);
    }

    // epilogue: write vn_{K-1}
    {
        const int plast = ((Kn - 1) & 1) ^ 1;
        float sfin = rsqrtf(g_dn2[plast]);
        for (int dd = tid; dd < nrows; dd += 256)
            g_VnT[(size_t)(d_lo + dd) * Kn + (Kn - 1)] = sfin * s_u[dd];
    }

    // reset barrier counter for the next graph replay (globally-last block)
    __syncthreads();
    if (tid == 0) {
        __threadfence();
        if (atomicAdd(&g_done, 1u) == (unsigned)(gridDim.x - 1)) {
            g_done = 0u;
            g_barcnt = 0u;
            __threadfence();
        }
    }
}

// ---------------- out = x @ VnT  ([8192,2048] x [2048,256]) ----------------
__global__ void __launch_bounds__(256) gemmOut_kernel(const float* __restrict__ x,
                                                      float* __restrict__ out) {
    __shared__ __align__(16) float As[16][132];
    __shared__ __align__(16) float Bs[16][64];

    const int br = blockIdx.x >> 2;
    const int bc = blockIdx.x & 3;
    const int tid = threadIdx.x;
    const int ty = tid >> 4, tx = tid & 15;
    const int n0 = br * 128;

    ull acc2[8][2];
    const ull z = splat2(0.f);
    #pragma unroll
    for (int p = 0; p < 8; ++p) { acc2[p][0] = z; acc2[p][1] = z; }

    for (int dchunk = 0; dchunk < Dn; dchunk += 16) {
        #pragma unroll
        for (int it = 0; it < 2; ++it) {
            int idx4 = tid + it * 256;
            int r = idx4 >> 2;
            int c4 = idx4 & 3;
            float4 v = *(const float4*)(x + (size_t)(n0 + r) * Dn + dchunk + c4 * 4);
            As[c4 * 4 + 0][r] = v.x;
            As[c4 * 4 + 1][r] = v.y;
            As[c4 * 4 + 2][r] = v.z;
            As[c4 * 4 + 3][r] = v.w;
        }
        {
            int kk = tid >> 4;
            int c4 = tid & 15;
            ((float4*)&Bs[kk][0])[c4] =
                *(const float4*)(&g_VnT[(size_t)(dchunk + kk) * Kn + bc * 64 + c4 * 4]);
        }
        __syncthreads();
        #pragma unroll
        for (int kk = 0; kk < 16; ++kk) {
            float a8[8];
            *(float4*)&a8[0] = *(const float4*)&As[kk][ty * 8];
            *(float4*)&a8[4] = *(const float4*)&As[kk][ty * 8 + 4];
            const ull* bp = (const ull*)&Bs[kk][tx * 4];
            ull b2[2] = { bp[0], bp[1] };
            #pragma unroll
            for (int p = 0; p < 8; ++p) {
                ull ap = splat2(a8[p]);
                fma2(acc2[p][0], ap, b2[0]);
                fma2(acc2[p][1], ap, b2[1]);
            }
        }
        __syncthreads();
    }

    #pragma unroll
    for (int p = 0; p < 8; ++p) {
        float2 v0 = *(float2*)&acc2[p][0];
        float2 v1 = *(float2*)&acc2[p][1];
        *(float4*)(out + (size_t)(n0 + ty * 8 + p) * Kn + bc * 64 + tx * 4) =
            make_float4(v0.x, v0.y, v1.x, v1.y);
    }
}

// ---------------- launch ----------------
extern "C" void kernel_launch(void* const* d_in, const int* in_sizes, int n_in,
                              void* d_out, int out_size) {
    const float* x  = (const float*)d_in[0];
    const float* V0 = (const float*)d_in[1];
    if (n_in >= 2 && in_sizes[0] == Dn * Kn && in_sizes[1] == Nn * Dn) {
        const float* t = x; x = V0; V0 = t;
    }
    float* out = (float*)d_out;

    static int smem_set = 0;
    const int dyn_smem = (ROWS_PB * Dn + 2 * ROWS_PB * Kn) * (int)sizeof(float); // 143360
    if (!smem_set) {
        cudaFuncSetAttribute(solve_kernel,
                             cudaFuncAttributeMaxDynamicSharedMemorySize, dyn_smem);
        smem_set = 1;
    }

    prep_kernel<<<Kn, 256>>>(V0);
    gemmC_kernel<<<136, 256>>>(x);
    solve_kernel<<<NBLK, 256, dyn_smem>>>();
    gemmOut_kernel<<<256, 256>>>(x, out);
}